// round 1
// baseline (speedup 1.0000x reference)
#include <cuda_runtime.h>

#define E_DIM 1024
#define NHEADS 16
#define DH 64
#define HH 128
#define WW 128
#define MROWS (HH * WW)              /* 16384 */
#define HWD ((size_t)MROWS * DH)     /* 1048576 per head-plane */

// ---------------- scratch (static device arrays; no allocation) ----------------
__device__ float g_q[(size_t)NHEADS * MROWS * DH];
__device__ float g_k[(size_t)NHEADS * MROWS * DH];
__device__ float g_v[(size_t)NHEADS * MROWS * DH];
__device__ float g_o1[(size_t)NHEADS * MROWS * DH];
__device__ float g_o2[(size_t)MROWS * E_DIM];

// =======================================================================
// SGEMM (TN): out[m,n] = sum_k A[m,k] * W[n,k] + bias[n]
// 128x128 block tile, BK=16, 256 threads, 8x8 per-thread microtile.
// HEADLAYOUT=1 writes out[(n/64)][m][n%64] (head-major scratch layout).
// =======================================================================
template <int HEADLAYOUT>
__device__ __forceinline__ void gemm_tile(const float* __restrict__ A,
                                          const float* __restrict__ Wt,
                                          const float* __restrict__ bias,
                                          float* __restrict__ out, bool relu) {
    __shared__ __align__(16) float As[16][132];
    __shared__ __align__(16) float Bs[16][132];

    const int tid = threadIdx.x;
    const int tx = tid & 15;        // 0..15 -> n microtile
    const int ty = tid >> 4;        // 0..15 -> m microtile
    const int m0 = blockIdx.x * 128;
    const int n0 = blockIdx.y * 128;
    const int lrow = tid >> 2;        // 0..63
    const int lcol = (tid & 3) << 2;  // 0,4,8,12

    float acc[8][8];
#pragma unroll
    for (int i = 0; i < 8; i++)
#pragma unroll
        for (int j = 0; j < 8; j++) acc[i][j] = 0.f;

    for (int k0 = 0; k0 < E_DIM; k0 += 16) {
#pragma unroll
        for (int it = 0; it < 2; it++) {
            int r = lrow + it * 64;
            float4 va = *reinterpret_cast<const float4*>(
                A + (size_t)(m0 + r) * E_DIM + k0 + lcol);
            As[lcol + 0][r] = va.x;
            As[lcol + 1][r] = va.y;
            As[lcol + 2][r] = va.z;
            As[lcol + 3][r] = va.w;
            float4 vb = *reinterpret_cast<const float4*>(
                Wt + (size_t)(n0 + r) * E_DIM + k0 + lcol);
            Bs[lcol + 0][r] = vb.x;
            Bs[lcol + 1][r] = vb.y;
            Bs[lcol + 2][r] = vb.z;
            Bs[lcol + 3][r] = vb.w;
        }
        __syncthreads();
#pragma unroll
        for (int kk = 0; kk < 16; kk++) {
            float a[8], b[8];
            float4 a0 = *reinterpret_cast<const float4*>(&As[kk][ty * 8]);
            float4 a1 = *reinterpret_cast<const float4*>(&As[kk][ty * 8 + 4]);
            float4 b0 = *reinterpret_cast<const float4*>(&Bs[kk][tx * 8]);
            float4 b1 = *reinterpret_cast<const float4*>(&Bs[kk][tx * 8 + 4]);
            a[0] = a0.x; a[1] = a0.y; a[2] = a0.z; a[3] = a0.w;
            a[4] = a1.x; a[5] = a1.y; a[6] = a1.z; a[7] = a1.w;
            b[0] = b0.x; b[1] = b0.y; b[2] = b0.z; b[3] = b0.w;
            b[4] = b1.x; b[5] = b1.y; b[6] = b1.z; b[7] = b1.w;
#pragma unroll
            for (int i = 0; i < 8; i++)
#pragma unroll
                for (int j = 0; j < 8; j++)
                    acc[i][j] = fmaf(a[i], b[j], acc[i][j]);
        }
        __syncthreads();
    }

#pragma unroll
    for (int i = 0; i < 8; i++) {
        int m = m0 + ty * 8 + i;
#pragma unroll
        for (int j = 0; j < 8; j++) {
            int n = n0 + tx * 8 + j;
            float v = acc[i][j] + bias[n];
            if (relu) v = fmaxf(v, 0.f);
            if (HEADLAYOUT)
                out[(size_t)(n >> 6) * HWD + (size_t)m * DH + (n & 63)] = v;
            else
                out[(size_t)m * E_DIM + n] = v;
        }
    }
}

__global__ __launch_bounds__(256) void qkv_kernel(
    const float* __restrict__ x, const float* __restrict__ Wq,
    const float* __restrict__ bq, const float* __restrict__ Wk,
    const float* __restrict__ bk, const float* __restrict__ Wv,
    const float* __restrict__ bv, float* gq, float* gk, float* gv) {
    const float* Wt;
    const float* bias;
    float* outp;
    bool relu;
    if (blockIdx.z == 0) {
        Wt = Wq; bias = bq; outp = gq; relu = true;
    } else if (blockIdx.z == 1) {
        Wt = Wk; bias = bk; outp = gk; relu = true;
    } else {
        Wt = Wv; bias = bv; outp = gv; relu = false;
    }
    gemm_tile<1>(x, Wt, bias, outp, relu);
}

__global__ __launch_bounds__(256) void out_kernel(
    const float* __restrict__ A, const float* __restrict__ W,
    const float* __restrict__ bias, float* __restrict__ out) {
    gemm_tile<0>(A, W, bias, out, false);
}

// =======================================================================
// Fused retention:
//   phase A: kv[d][e] = sum_{r=0..127} k[r][d] * v[r][e]  (regs -> smem)
//   phase B: out[r][e] = sum_d c[r][d] * kv[d][e]
// mode 0: block=(h,head); r runs over w (contiguous rows, stride 64)
// mode 1: block=(w,head); r runs over h (stride 128*64); out -> [M,E] layout
// =======================================================================
__global__ __launch_bounds__(256) void retention_kernel(
    const float* __restrict__ kArr, const float* __restrict__ vArr,
    const float* __restrict__ cArr, float* __restrict__ oArr, int mode) {
    __shared__ __align__(16) float sm[2 * 64 * 68];
    float* ks = sm;              // phase A: [32][68]
    float* vs = sm + 32 * 68;    // phase A: [32][68]
    float* kvs = sm;             // phase B: [64][68] (reuses A region)
    float* qs = sm + 64 * 68;    // phase B: [64][68]

    const int tid = threadIdx.x;
    const int tx = tid & 15;   // e microtile
    const int ty = tid >> 4;   // d / r microtile
    const int b = blockIdx.x;
    const int n = b & 15;
    const int idx = b >> 4;

    size_t base, obase;
    int rs, ors;
    if (mode == 0) {
        base = (size_t)n * HWD + (size_t)idx * (WW * DH);
        rs = DH;
        obase = base;
        ors = DH;
    } else {
        base = (size_t)n * HWD + (size_t)idx * DH;
        rs = WW * DH;              // 8192
        obase = (size_t)idx * E_DIM + n * DH;
        ors = WW * E_DIM;          // 131072
    }
    const float* kS = kArr + base;
    const float* vS = vArr + base;
    const float* cS = cArr + base;
    float* oD = oArr + obase;

    // ---- phase A ----
    float acc[4][4];
#pragma unroll
    for (int i = 0; i < 4; i++)
#pragma unroll
        for (int j = 0; j < 4; j++) acc[i][j] = 0.f;

    for (int rc = 0; rc < 4; rc++) {
#pragma unroll
        for (int it = 0; it < 2; it++) {
            int f = tid + it * 256;
            int row = f >> 4;          // 0..31
            int c = (f & 15) << 2;     // 0..60
            size_t gidx = (size_t)(rc * 32 + row) * rs + c;
            *reinterpret_cast<float4*>(&ks[row * 68 + c]) =
                *reinterpret_cast<const float4*>(&kS[gidx]);
            *reinterpret_cast<float4*>(&vs[row * 68 + c]) =
                *reinterpret_cast<const float4*>(&vS[gidx]);
        }
        __syncthreads();
#pragma unroll 8
        for (int r = 0; r < 32; r++) {
            float4 av = *reinterpret_cast<const float4*>(&ks[r * 68 + ty * 4]);
            float4 bv = *reinterpret_cast<const float4*>(&vs[r * 68 + tx * 4]);
            float a[4] = {av.x, av.y, av.z, av.w};
            float bb[4] = {bv.x, bv.y, bv.z, bv.w};
#pragma unroll
            for (int i = 0; i < 4; i++)
#pragma unroll
                for (int j = 0; j < 4; j++)
                    acc[i][j] = fmaf(a[i], bb[j], acc[i][j]);
        }
        __syncthreads();
    }

    // stage kv into smem (safe: all phase-A reads completed at last barrier)
#pragma unroll
    for (int i = 0; i < 4; i++) {
        float4 t = make_float4(acc[i][0], acc[i][1], acc[i][2], acc[i][3]);
        *reinterpret_cast<float4*>(&kvs[(ty * 4 + i) * 68 + tx * 4]) = t;
    }
    __syncthreads();

    // ---- phase B ----
    for (int wc = 0; wc < 2; wc++) {
#pragma unroll
        for (int it = 0; it < 4; it++) {
            int f = tid + it * 256;
            int row = f >> 4;        // 0..63
            int c = (f & 15) << 2;
            *reinterpret_cast<float4*>(&qs[row * 68 + c]) =
                *reinterpret_cast<const float4*>(
                    &cS[(size_t)(wc * 64 + row) * rs + c]);
        }
        __syncthreads();

        float o[4][4];
#pragma unroll
        for (int i = 0; i < 4; i++)
#pragma unroll
            for (int j = 0; j < 4; j++) o[i][j] = 0.f;

#pragma unroll 4
        for (int d = 0; d < 64; d++) {
            float4 bv = *reinterpret_cast<const float4*>(&kvs[d * 68 + tx * 4]);
            float bb[4] = {bv.x, bv.y, bv.z, bv.w};
            float a[4];
#pragma unroll
            for (int i = 0; i < 4; i++) a[i] = qs[(ty * 4 + i) * 68 + d];
#pragma unroll
            for (int i = 0; i < 4; i++)
#pragma unroll
                for (int j = 0; j < 4; j++)
                    o[i][j] = fmaf(a[i], bb[j], o[i][j]);
        }

#pragma unroll
        for (int i = 0; i < 4; i++) {
            int r = wc * 64 + ty * 4 + i;
            float4 t = make_float4(o[i][0], o[i][1], o[i][2], o[i][3]);
            *reinterpret_cast<float4*>(&oD[(size_t)r * ors + tx * 4]) = t;
        }
        __syncthreads();
    }
}

// =======================================================================
extern "C" void kernel_launch(void* const* d_in, const int* in_sizes, int n_in,
                              void* d_out, int out_size) {
    const float* x  = (const float*)d_in[0];
    const float* Wq = (const float*)d_in[1];
    const float* bq = (const float*)d_in[2];
    const float* Wk = (const float*)d_in[3];
    const float* bk = (const float*)d_in[4];
    const float* Wv = (const float*)d_in[5];
    const float* bv = (const float*)d_in[6];
    const float* Wo = (const float*)d_in[7];
    const float* bo = (const float*)d_in[8];
    float* out = (float*)d_out;

    float *gq, *gk, *gv, *go1, *go2;
    cudaGetSymbolAddress((void**)&gq, g_q);
    cudaGetSymbolAddress((void**)&gk, g_k);
    cudaGetSymbolAddress((void**)&gv, g_v);
    cudaGetSymbolAddress((void**)&go1, g_o1);
    cudaGetSymbolAddress((void**)&go2, g_o2);

    dim3 blk(256);
    dim3 gqkv(MROWS / 128, E_DIM / 128, 3);
    qkv_kernel<<<gqkv, blk>>>(x, Wq, bq, Wk, bk, Wv, bv, gq, gk, gv);
    retention_kernel<<<HH * NHEADS, blk>>>(gk, gv, gq, go1, 0);
    retention_kernel<<<WW * NHEADS, blk>>>(gk, gv, go1, go2, 1);
    dim3 gout(MROWS / 128, E_DIM / 128, 1);
    out_kernel<<<gout, blk>>>(go2, Wo, bo, out);
}

// round 3
// speedup vs baseline: 2.1332x; 2.1332x over previous
#include <cuda_runtime.h>
#include <cuda_bf16.h>
#include <cstdint>

#define E_DIM 1024
#define K3 (3 * E_DIM)               /* 3072 concat-K */
#define NHEADS 16
#define DH 64
#define HH 128
#define WW 128
#define MROWS (HH * WW)              /* 16384 */
#define HWD ((size_t)MROWS * DH)

// ---------------- scratch (static device arrays; no allocation) ----------------
__device__ __nv_bfloat16 g_a2[(size_t)MROWS * K3];        // [Ah|Al|Ah] of x
__device__ __nv_bfloat16 g_b2[4][(size_t)E_DIM * K3];     // [Wh|Wh|Wl] per weight
__device__ __nv_bfloat16 g_o2cat[(size_t)MROWS * K3];     // [hi|lo|hi] of o2
__device__ float g_q[(size_t)NHEADS * MROWS * DH];
__device__ float g_k[(size_t)NHEADS * MROWS * DH];
__device__ float g_v[(size_t)NHEADS * MROWS * DH];
__device__ float g_o1[(size_t)NHEADS * MROWS * DH];

// ======================= helpers =======================
__device__ __forceinline__ uint32_t smem_u32(const void* p) {
    uint32_t a;
    asm("{ .reg .u64 t; cvta.to.shared.u64 t, %1; cvt.u32.u64 %0, t; }"
        : "=r"(a) : "l"(p));
    return a;
}

__device__ __forceinline__ void cp_async16(uint32_t dst, const void* src) {
    asm volatile("cp.async.cg.shared.global [%0], [%1], 16;\n"
                 :: "r"(dst), "l"(src) : "memory");
}

__device__ __forceinline__ void ldm_x4(uint32_t* r, uint32_t addr) {
    asm volatile(
        "ldmatrix.sync.aligned.m8n8.x4.shared.b16 {%0,%1,%2,%3}, [%4];"
        : "=r"(r[0]), "=r"(r[1]), "=r"(r[2]), "=r"(r[3]) : "r"(addr));
}

__device__ __forceinline__ void mma_bf16(float* c, const uint32_t* a,
                                         const uint32_t* b) {
    asm volatile(
        "mma.sync.aligned.m16n8k16.row.col.f32.bf16.bf16.f32 "
        "{%0,%1,%2,%3}, {%4,%5,%6,%7}, {%8,%9}, {%0,%1,%2,%3};"
        : "+f"(c[0]), "+f"(c[1]), "+f"(c[2]), "+f"(c[3])
        : "r"(a[0]), "r"(a[1]), "r"(a[2]), "r"(a[3]), "r"(b[0]), "r"(b[1]));
}

// ======================= bf16 HMMA GEMM =======================
// D[m,n] = sum_{k<3072} A2[m,k] * B2[n,k] + bias[n]
// CTA tile 128x128, 8 warps (4m x 2n), warp tile 32x64, K-chunk 32, dbl buf.
// HEADLAYOUT=1: out[(n>>6)*HWD + m*64 + (n&63)]; else out[m*E + n].
#define ROWP 40  /* padded row length in bf16 (80B) */

template <int HEADLAYOUT>
__device__ __forceinline__ void mma_gemm_body(
    const __nv_bfloat16* __restrict__ A2, const __nv_bfloat16* __restrict__ B2,
    const float* __restrict__ bias, float* __restrict__ out, bool relu) {
    __shared__ __align__(16) __nv_bfloat16 As[2][128 * ROWP];
    __shared__ __align__(16) __nv_bfloat16 Bs[2][128 * ROWP];

    const int tid = threadIdx.x;
    const int wid = tid >> 5;
    const int lane = tid & 31;
    const int wm = wid & 3;   // 0..3 (m)
    const int wn = wid >> 2;  // 0..1 (n)
    const int m0 = blockIdx.x * 128;
    const int n0 = blockIdx.y * 128;

    const int ldrow = tid >> 2;         // 0..63
    const int ldseg = (tid & 3) * 8;    // element offset within row

    float acc[2][8][4];
#pragma unroll
    for (int i = 0; i < 2; i++)
#pragma unroll
        for (int j = 0; j < 8; j++)
#pragma unroll
            for (int c = 0; c < 4; c++) acc[i][j][c] = 0.f;

    auto load_chunk = [&](int buf, int k0) {
#pragma unroll
        for (int i = 0; i < 2; i++) {
            int row = ldrow + i * 64;
            uint32_t da = smem_u32(&As[buf][row * ROWP + ldseg]);
            cp_async16(da, A2 + (size_t)(m0 + row) * K3 + k0 + ldseg);
            uint32_t db = smem_u32(&Bs[buf][row * ROWP + ldseg]);
            cp_async16(db, B2 + (size_t)(n0 + row) * K3 + k0 + ldseg);
        }
    };

    load_chunk(0, 0);
    asm volatile("cp.async.commit_group;\n" ::: "memory");

    // ldmatrix lane addressing (element offsets, x2 for bytes applied later)
    const int a_row = lane & 15;          // within 16-row tile
    const int a_c8 = (lane >> 4) * 8;     // 0 or 8 (k)
    const int b_row = (lane & 7) | ((lane & 16) >> 1);  // n within 16
    const int b_c8 = ((lane >> 3) & 1) * 8;             // 0 or 8 (k)

    for (int ch = 0; ch < 96; ch++) {
        if (ch + 1 < 96) {
            load_chunk((ch + 1) & 1, (ch + 1) * 32);
            asm volatile("cp.async.commit_group;\n" ::: "memory");
            asm volatile("cp.async.wait_group 1;\n" ::: "memory");
        } else {
            asm volatile("cp.async.wait_group 0;\n" ::: "memory");
        }
        __syncthreads();

        const int buf = ch & 1;
        const uint32_t sbA = smem_u32(&As[buf][0]);
        const uint32_t sbB = smem_u32(&Bs[buf][0]);

#pragma unroll
        for (int kk = 0; kk < 2; kk++) {
            uint32_t a[2][4], b[8][2];
#pragma unroll
            for (int mt = 0; mt < 2; mt++) {
                uint32_t addr = sbA +
                    2 * ((32 * wm + 16 * mt + a_row) * ROWP + kk * 16 + a_c8);
                ldm_x4(a[mt], addr);
            }
#pragma unroll
            for (int np = 0; np < 4; np++) {
                uint32_t r[4];
                uint32_t addr = sbB +
                    2 * ((64 * wn + 16 * np + b_row) * ROWP + kk * 16 + b_c8);
                ldm_x4(r, addr);
                b[np * 2][0] = r[0]; b[np * 2][1] = r[1];
                b[np * 2 + 1][0] = r[2]; b[np * 2 + 1][1] = r[3];
            }
#pragma unroll
            for (int mt = 0; mt < 2; mt++)
#pragma unroll
                for (int nt = 0; nt < 8; nt++)
                    mma_bf16(acc[mt][nt], a[mt], b[nt]);
        }
        __syncthreads();
    }

    // ---------------- epilogue ----------------
    const int g = lane >> 2;
    const int tq = lane & 3;
#pragma unroll
    for (int nt = 0; nt < 8; nt++) {
        const int n = n0 + 64 * wn + 8 * nt + 2 * tq;
        const float b0 = __ldg(bias + n);
        const float b1 = __ldg(bias + n + 1);
#pragma unroll
        for (int mt = 0; mt < 2; mt++) {
            const int mbase = m0 + 32 * wm + 16 * mt + g;
#pragma unroll
            for (int half = 0; half < 2; half++) {
                const int m = mbase + half * 8;
                float v0 = acc[mt][nt][half * 2] + b0;
                float v1 = acc[mt][nt][half * 2 + 1] + b1;
                if (relu) { v0 = fmaxf(v0, 0.f); v1 = fmaxf(v1, 0.f); }
                float2 t = make_float2(v0, v1);
                if (HEADLAYOUT) {
                    *reinterpret_cast<float2*>(
                        out + (size_t)(n >> 6) * HWD + (size_t)m * 64 +
                        (n & 63)) = t;
                } else {
                    *reinterpret_cast<float2*>(out + (size_t)m * E_DIM + n) = t;
                }
            }
        }
    }
}

__global__ __launch_bounds__(256) void qkv_mma_kernel(
    const __nv_bfloat16* __restrict__ a2, const __nv_bfloat16* __restrict__ b2,
    const float* __restrict__ bq, const float* __restrict__ bk,
    const float* __restrict__ bv, float* gq, float* gk, float* gv) {
    const size_t WSZ = (size_t)E_DIM * K3;
    const __nv_bfloat16* B = b2 + (size_t)blockIdx.z * WSZ;
    const float* bias;
    float* outp;
    bool relu;
    if (blockIdx.z == 0) { bias = bq; outp = gq; relu = true; }
    else if (blockIdx.z == 1) { bias = bk; outp = gk; relu = true; }
    else { bias = bv; outp = gv; relu = false; }
    mma_gemm_body<1>(a2, B, bias, outp, relu);
}

__global__ __launch_bounds__(256) void out_mma_kernel(
    const __nv_bfloat16* __restrict__ a2, const __nv_bfloat16* __restrict__ b2,
    const float* __restrict__ bias, float* __restrict__ out) {
    mma_gemm_body<0>(a2, b2, bias, out, false);
}

// ======================= fp32 -> split-bf16 concat =======================
// MODEA=1: [hi | lo | hi]  (A operand); MODEA=0: [hi | hi | lo]  (B operand)
template <int MODEA>
__global__ __launch_bounds__(256) void split_kernel(
    const float* __restrict__ in, __nv_bfloat16* __restrict__ out, int total) {
    int i = (blockIdx.x * 256 + threadIdx.x) * 4;
    if (i >= total) return;
    float4 v = *reinterpret_cast<const float4*>(in + i);
    float f[4] = {v.x, v.y, v.z, v.w};
    __nv_bfloat16 h[4], l[4];
#pragma unroll
    for (int j = 0; j < 4; j++) {
        h[j] = __float2bfloat16(f[j]);
        l[j] = __float2bfloat16(f[j] - __bfloat162float(h[j]));
    }
    int row = i >> 10;
    int k = i & 1023;
    __nv_bfloat16* base = out + (size_t)row * K3 + k;
    __nv_bfloat162 hp0(h[0], h[1]), hp1(h[2], h[3]);
    __nv_bfloat162 lp0(l[0], l[1]), lp1(l[2], l[3]);
    __nv_bfloat162* p0 = reinterpret_cast<__nv_bfloat162*>(base);
    __nv_bfloat162* p1 = reinterpret_cast<__nv_bfloat162*>(base + E_DIM);
    __nv_bfloat162* p2 = reinterpret_cast<__nv_bfloat162*>(base + 2 * E_DIM);
    p0[0] = hp0; p0[1] = hp1;
    if (MODEA) {
        p1[0] = lp0; p1[1] = lp1;
        p2[0] = hp0; p2[1] = hp1;
    } else {
        p1[0] = hp0; p1[1] = hp1;
        p2[0] = lp0; p2[1] = lp1;
    }
}

// ======================= fused retention (fp32) =======================
// mode 0: block=(h,head), reduce over w; write fp32 o1 (head layout)
// mode 1: block=(w,head), reduce over h; write split-bf16 concat o2cat
__global__ __launch_bounds__(256) void retention_kernel(
    const float* __restrict__ kArr, const float* __restrict__ vArr,
    const float* __restrict__ cArr, float* __restrict__ oF,
    __nv_bfloat16* __restrict__ oCat, int mode) {
    __shared__ __align__(16) float sm[2 * 64 * 68];
    float* ks = sm;
    float* vs = sm + 32 * 68;
    float* kvs = sm;
    float* qs = sm + 64 * 68;

    const int tid = threadIdx.x;
    const int tx = tid & 15;
    const int ty = tid >> 4;
    const int b = blockIdx.x;
    const int n = b & 15;
    const int idx = b >> 4;

    size_t base;
    int rs;
    if (mode == 0) {
        base = (size_t)n * HWD + (size_t)idx * (WW * DH);
        rs = DH;
    } else {
        base = (size_t)n * HWD + (size_t)idx * DH;
        rs = WW * DH;
    }
    const float* kS = kArr + base;
    const float* vS = vArr + base;
    const float* cS = cArr + base;

    float acc[4][4];
#pragma unroll
    for (int i = 0; i < 4; i++)
#pragma unroll
        for (int j = 0; j < 4; j++) acc[i][j] = 0.f;

    for (int rc = 0; rc < 4; rc++) {
#pragma unroll
        for (int it = 0; it < 2; it++) {
            int f = tid + it * 256;
            int row = f >> 4;
            int c = (f & 15) << 2;
            size_t gidx = (size_t)(rc * 32 + row) * rs + c;
            *reinterpret_cast<float4*>(&ks[row * 68 + c]) =
                *reinterpret_cast<const float4*>(&kS[gidx]);
            *reinterpret_cast<float4*>(&vs[row * 68 + c]) =
                *reinterpret_cast<const float4*>(&vS[gidx]);
        }
        __syncthreads();
#pragma unroll 8
        for (int r = 0; r < 32; r++) {
            float4 av = *reinterpret_cast<const float4*>(&ks[r * 68 + ty * 4]);
            float4 bvv = *reinterpret_cast<const float4*>(&vs[r * 68 + tx * 4]);
            float a[4] = {av.x, av.y, av.z, av.w};
            float bb[4] = {bvv.x, bvv.y, bvv.z, bvv.w};
#pragma unroll
            for (int i = 0; i < 4; i++)
#pragma unroll
                for (int j = 0; j < 4; j++)
                    acc[i][j] = fmaf(a[i], bb[j], acc[i][j]);
        }
        __syncthreads();
    }

#pragma unroll
    for (int i = 0; i < 4; i++) {
        float4 t = make_float4(acc[i][0], acc[i][1], acc[i][2], acc[i][3]);
        *reinterpret_cast<float4*>(&kvs[(ty * 4 + i) * 68 + tx * 4]) = t;
    }
    __syncthreads();

    for (int wc = 0; wc < 2; wc++) {
#pragma unroll
        for (int it = 0; it < 4; it++) {
            int f = tid + it * 256;
            int row = f >> 4;
            int c = (f & 15) << 2;
            *reinterpret_cast<float4*>(&qs[row * 68 + c]) =
                *reinterpret_cast<const float4*>(
                    &cS[(size_t)(wc * 64 + row) * rs + c]);
        }
        __syncthreads();

        float o[4][4];
#pragma unroll
        for (int i = 0; i < 4; i++)
#pragma unroll
            for (int j = 0; j < 4; j++) o[i][j] = 0.f;

#pragma unroll 4
        for (int d = 0; d < 64; d++) {
            float4 bvv = *reinterpret_cast<const float4*>(&kvs[d * 68 + tx * 4]);
            float bb[4] = {bvv.x, bvv.y, bvv.z, bvv.w};
            float a[4];
#pragma unroll
            for (int i = 0; i < 4; i++) a[i] = qs[(ty * 4 + i) * 68 + d];
#pragma unroll
            for (int i = 0; i < 4; i++)
#pragma unroll
                for (int j = 0; j < 4; j++)
                    o[i][j] = fmaf(a[i], bb[j], o[i][j]);
        }

#pragma unroll
        for (int i = 0; i < 4; i++) {
            int r = wc * 64 + ty * 4 + i;
            if (mode == 0) {
                size_t oidx = base + (size_t)r * DH + tx * 4;
                float4 t = make_float4(o[i][0], o[i][1], o[i][2], o[i][3]);
                *reinterpret_cast<float4*>(&oF[oidx]) = t;
            } else {
                // global row m = r*WW + idx, col e = n*64 + tx*4
                int m = r * WW + idx;
                int e = n * DH + tx * 4;
                __nv_bfloat16 h[4], l[4];
#pragma unroll
                for (int j = 0; j < 4; j++) {
                    h[j] = __float2bfloat16(o[i][j]);
                    l[j] = __float2bfloat16(o[i][j] - __bfloat162float(h[j]));
                }
                __nv_bfloat16* bp = oCat + (size_t)m * K3 + e;
                __nv_bfloat162 hp0(h[0], h[1]), hp1(h[2], h[3]);
                __nv_bfloat162 lp0(l[0], l[1]), lp1(l[2], l[3]);
                reinterpret_cast<__nv_bfloat162*>(bp)[0] = hp0;
                reinterpret_cast<__nv_bfloat162*>(bp)[1] = hp1;
                reinterpret_cast<__nv_bfloat162*>(bp + E_DIM)[0] = lp0;
                reinterpret_cast<__nv_bfloat162*>(bp + E_DIM)[1] = lp1;
                reinterpret_cast<__nv_bfloat162*>(bp + 2 * E_DIM)[0] = hp0;
                reinterpret_cast<__nv_bfloat162*>(bp + 2 * E_DIM)[1] = hp1;
            }
        }
        __syncthreads();
    }
}

// =======================================================================
extern "C" void kernel_launch(void* const* d_in, const int* in_sizes, int n_in,
                              void* d_out, int out_size) {
    const float* x  = (const float*)d_in[0];
    const float* Wq = (const float*)d_in[1];
    const float* bq = (const float*)d_in[2];
    const float* Wk = (const float*)d_in[3];
    const float* bk = (const float*)d_in[4];
    const float* Wv = (const float*)d_in[5];
    const float* bv = (const float*)d_in[6];
    const float* Wo = (const float*)d_in[7];
    const float* bo = (const float*)d_in[8];
    float* out = (float*)d_out;

    __nv_bfloat16 *a2, *b2, *o2cat;
    float *gq, *gk, *gv, *go1;
    cudaGetSymbolAddress((void**)&a2, g_a2);
    cudaGetSymbolAddress((void**)&b2, g_b2);
    cudaGetSymbolAddress((void**)&o2cat, g_o2cat);
    cudaGetSymbolAddress((void**)&gq, g_q);
    cudaGetSymbolAddress((void**)&gk, g_k);
    cudaGetSymbolAddress((void**)&gv, g_v);
    cudaGetSymbolAddress((void**)&go1, g_o1);

    const size_t WSZ = (size_t)E_DIM * K3;
    const int WTOT = E_DIM * E_DIM;

    // splits
    int nx = MROWS * E_DIM;
    split_kernel<1><<<nx / 1024, 256>>>(x, a2, nx);
    split_kernel<0><<<WTOT / 1024, 256>>>(Wq, b2 + 0 * WSZ, WTOT);
    split_kernel<0><<<WTOT / 1024, 256>>>(Wk, b2 + 1 * WSZ, WTOT);
    split_kernel<0><<<WTOT / 1024, 256>>>(Wv, b2 + 2 * WSZ, WTOT);
    split_kernel<0><<<WTOT / 1024, 256>>>(Wo, b2 + 3 * WSZ, WTOT);

    // q/k/v projections (HMMA)
    dim3 gqkv(MROWS / 128, E_DIM / 128, 3);
    qkv_mma_kernel<<<gqkv, 256>>>(a2, b2, bq, bk, bv, gq, gk, gv);

    // retention (fp32)
    retention_kernel<<<HH * NHEADS, 256>>>(gk, gv, gq, go1, nullptr, 0);
    retention_kernel<<<WW * NHEADS, 256>>>(gk, gv, go1, nullptr, o2cat, 1);

    // output projection (HMMA)
    dim3 gout(MROWS / 128, E_DIM / 128, 1);
    out_mma_kernel<<<gout, 256>>>(o2cat, b2 + 3 * WSZ, bo, out);
}